// round 4
// baseline (speedup 1.0000x reference)
#include <cuda_runtime.h>
#include <cstddef>

// ---------------------------------------------------------------------------
// ContextNet (RIFE-style) on GB300 — padded buffers + packed f32x2 FMA conv.
// Levels: (Cin,Cout,Hin): (3,16,512) (16,32,256) (32,64,128) (64,128,64)
// ---------------------------------------------------------------------------

#define NB 16  // batch

__device__ float g_fa[33000000];
__device__ float g_fb[33000000];
__device__ float g_flA[(size_t)16 * 2 * 256 * 256];
__device__ float g_flB[(size_t)16 * 2 * 256 * 256];
__device__ float g_cnt[(size_t)16 * 256 * 256];

// ---- f32x2 helpers (Blackwell packed dual-fp32) ---------------------------
__device__ __forceinline__ unsigned long long f32x2_dup(float v) {
    unsigned long long r;
    unsigned int u = __float_as_uint(v);
    asm("mov.b64 %0, {%1, %1};" : "=l"(r) : "r"(u));
    return r;
}
__device__ __forceinline__ void fma2(unsigned long long& d,
                                     unsigned long long a,
                                     unsigned long long b) {
    asm("fma.rn.f32x2 %0, %1, %2, %0;" : "+l"(d) : "l"(a), "l"(b));
}
__device__ __forceinline__ float2 f32x2_unpack(unsigned long long v) {
    unsigned int lo, hi;
    asm("mov.b64 {%0, %1}, %2;" : "=r"(lo), "=r"(hi) : "l"(v));
    return make_float2(__uint_as_float(lo), __uint_as_float(hi));
}

// ---------------------------------------------------------------------------
// Zero the 1-px border of NC padded planes of logical size HxW (pitch W+2).
// ---------------------------------------------------------------------------
__global__ void zero_border_kernel(float* __restrict__ base, int NC, int H, int W) {
    int per = 2 * (W + 2) + 2 * H;
    int idx = blockIdx.x * blockDim.x + threadIdx.x;
    if (idx >= NC * per) return;
    int c = idx / per, r = idx % per;
    float* p = base + (size_t)c * (H + 2) * (W + 2);
    if (r < W + 2) {
        p[r] = 0.f;
    } else if (r < 2 * (W + 2)) {
        p[(size_t)(H + 1) * (W + 2) + (r - (W + 2))] = 0.f;
    } else {
        int rr = r - 2 * (W + 2);
        int y = rr % H;
        bool right = rr >= H;
        p[(size_t)(y + 1) * (W + 2) + (right ? (W + 1) : 0)] = 0.f;
    }
}

// ---------------------------------------------------------------------------
// 3x3 conv + bias + PReLU with packed f32x2 accumulation.
// Each thread: 4 output channels (as 2 f32x2 pairs) x ROWS rows.
// Block (32,8); tile 32 x 8*ROWS. Grid (Wout/32, Hout/(8*ROWS), NB*Cout/4).
// Shared weights stored channel-PAIRED: sw2[(cp*Cin+ci)*9+k] = {w[2cp],w[2cp+1]}
// ---------------------------------------------------------------------------
template <int STRIDE, int ROWS, bool PRED>
__global__ void conv3x3_prelu(const float* __restrict__ in,
                              const float* __restrict__ wt,
                              const float* __restrict__ bias,
                              const float* __restrict__ alpha,
                              float* __restrict__ out,
                              int Cin, int Cout, int Hin, int Win,
                              int inPitch, size_t inPlane,
                              int outPitch, size_t outPlane) {
    const int cg = Cout >> 2;
    const int co0 = (blockIdx.z % cg) * 4;
    const int n   = blockIdx.z / cg;

    extern __shared__ float2 sw2[];          // [2][Cin][9] float2
    const int tid = threadIdx.y * 32 + threadIdx.x;
    const int nw = 2 * Cin * 9;
    for (int i = tid; i < nw; i += 256) {
        int k  = i % 9;
        int ci = (i / 9) % Cin;
        int cp = i / (9 * Cin);
        const float* wb = wt + ((size_t)(co0 + 2 * cp) * Cin + ci) * 9 + k;
        sw2[i] = make_float2(wb[0], wb[(size_t)Cin * 9]);
    }
    __syncthreads();

    const int x  = blockIdx.x * 32 + threadIdx.x;
    const int y0 = blockIdx.y * (8 * ROWS) + threadIdx.y * ROWS;

    unsigned long long acc2[2][ROWS];
#pragma unroll
    for (int cp = 0; cp < 2; cp++)
#pragma unroll
        for (int j = 0; j < ROWS; j++) acc2[cp][j] = 0ull;

    const float* ib = in + (size_t)n * Cin * inPlane;
    constexpr int NR = (STRIDE == 1) ? (ROWS + 2) : (2 * ROWS + 1);

    for (int ci = 0; ci < Cin; ci++) {
        const float* ip = ib + (size_t)ci * inPlane;
        const unsigned long long* wp =
            reinterpret_cast<const unsigned long long*>(sw2) + (size_t)ci * 9;
        const unsigned long long* wp1 = wp + (size_t)Cin * 9;
#pragma unroll
        for (int c = 0; c < 3; c++) {
            // load one input column (duplicated into f32x2 lanes)
            unsigned long long vv[NR];
#pragma unroll
            for (int r = 0; r < NR; r++) {
                const int iy = STRIDE * y0 - 1 + r;
                const int ix = STRIDE * x - 1 + c;
                float v;
                if (PRED) {
                    bool ok = ((unsigned)iy < (unsigned)Hin) &&
                              ((unsigned)ix < (unsigned)Win);
                    v = ok ? ip[(ptrdiff_t)iy * inPitch + ix] : 0.f;
                } else {
                    v = ip[(ptrdiff_t)iy * inPitch + ix];
                }
                vv[r] = f32x2_dup(v);
            }
#pragma unroll
            for (int ky = 0; ky < 3; ky++) {
                unsigned long long w0 = wp[ky * 3 + c];
                unsigned long long w1 = wp1[ky * 3 + c];
#pragma unroll
                for (int j = 0; j < ROWS; j++) {
                    fma2(acc2[0][j], vv[STRIDE * j + ky], w0);
                    fma2(acc2[1][j], vv[STRIDE * j + ky], w1);
                }
            }
        }
    }

#pragma unroll
    for (int cp = 0; cp < 2; cp++) {
        const int coA = co0 + 2 * cp;
        const int coB = coA + 1;
        const float bA = bias[coA], bB = bias[coB];
        const float aA = alpha[coA], aB = alpha[coB];
        float* obA = out + (size_t)(n * Cout + coA) * outPlane;
        float* obB = out + (size_t)(n * Cout + coB) * outPlane;
#pragma unroll
        for (int j = 0; j < ROWS; j++) {
            float2 v = f32x2_unpack(acc2[cp][j]);
            float oA = v.x + bA; oA = (oA >= 0.f) ? oA : aA * oA;
            float oB = v.y + bB; oB = (oB >= 0.f) ? oB : aB * oB;
            obA[(size_t)(y0 + j) * outPitch + x] = oA;
            obB[(size_t)(y0 + j) * outPitch + x] = oB;
        }
    }
}

// ---------------------------------------------------------------------------
// Flow halving: 2x2 mean * 0.5 == sum * 0.125
// ---------------------------------------------------------------------------
__global__ void halve_flow_kernel(const float* __restrict__ in,
                                  float* __restrict__ out, int Hout, int Wout) {
    int idx = blockIdx.x * blockDim.x + threadIdx.x;
    int total = NB * 2 * Hout * Wout;
    if (idx >= total) return;
    int w = idx % Wout;
    int h = (idx / Wout) % Hout;
    int nc = idx / (Wout * Hout);
    int Win = 2 * Wout;
    const float* ip = in + (size_t)nc * (4 * Hout * Wout);
    const float* r0 = ip + (2 * h) * Win + 2 * w;
    const float* r1 = r0 + Win;
    out[idx] = (r0[0] + r0[1] + r1[0] + r1[1]) * 0.125f;
}

// ---------------------------------------------------------------------------
// Forward bilinear splat. feat is a PADDED region (pitch W+2).
// ---------------------------------------------------------------------------
__global__ void splat_add_kernel(const float* __restrict__ feat,
                                 const float* __restrict__ flow,
                                 float* __restrict__ num,
                                 float* __restrict__ cnt,
                                 int C, int H, int W) {
    int idx = blockIdx.x * blockDim.x + threadIdx.x;
    int HW = H * W;
    int total = NB * HW;
    if (idx >= total) return;
    int n = idx / HW;
    int p = idx % HW;
    int y = p / W;
    int x = p % W;

    const float* fb = flow + (size_t)n * 2 * HW;
    float fx = fb[p] + (float)x;
    float fy = fb[HW + p] + (float)y;

    float x0f = floorf(fx), y0f = floorf(fy);
    int ix0 = (int)x0f, iy0 = (int)y0f;
    float wx1 = fx - x0f, wy1 = fy - y0f;
    float wx0 = 1.f - wx1, wy0 = 1.f - wy1;

    int   xi[4] = {ix0, ix0 + 1, ix0,     ix0 + 1};
    int   yi[4] = {iy0, iy0,     iy0 + 1, iy0 + 1};
    float wv[4] = {wx0 * wy0, wx1 * wy0, wx0 * wy1, wx1 * wy1};
    int   tgt[4];
    bool  ok[4];
#pragma unroll
    for (int k = 0; k < 4; k++) {
        ok[k] = ((unsigned)xi[k] < (unsigned)W) && ((unsigned)yi[k] < (unsigned)H);
        tgt[k] = yi[k] * W + xi[k];
        if (ok[k]) atomicAdd(&cnt[n * HW + tgt[k]], wv[k]);
    }

    const size_t plane = (size_t)(H + 2) * (W + 2);
    const float* src = feat + (size_t)n * C * plane + (size_t)(y + 1) * (W + 2) + (x + 1);
    float* dst = num + (size_t)n * C * HW;
    for (int c = 0; c < C; c++) {
        float s = src[(size_t)c * plane];
        float* dc = dst + (size_t)c * HW;
#pragma unroll
        for (int k = 0; k < 4; k++)
            if (ok[k]) atomicAdd(&dc[tgt[k]], s * wv[k]);
    }
}

// ---------------------------------------------------------------------------
// num /= (cnt == 0 ? 1 : cnt)
// ---------------------------------------------------------------------------
__global__ void norm_div_kernel(float* __restrict__ num,
                                const float* __restrict__ cnt,
                                int C, int HW) {
    int idx = blockIdx.x * blockDim.x + threadIdx.x;
    int total = NB * C * HW;
    if (idx >= total) return;
    int n = idx / (C * HW);
    int p = idx % HW;
    float cv = cnt[n * HW + p];
    num[idx] = num[idx] / ((cv == 0.f) ? 1.f : cv);
}

// ---------------------------------------------------------------------------
// Host launcher
// ---------------------------------------------------------------------------
extern "C" void kernel_launch(void* const* d_in, const int* in_sizes, int n_in,
                              void* d_out, int out_size) {
    const float* img  = (const float*)d_in[0];
    const float* flow = (const float*)d_in[1];
    float* out = (float*)d_out;

    float *fa, *fb, *flA, *flB, *cnt;
    cudaGetSymbolAddress((void**)&fa,  g_fa);
    cudaGetSymbolAddress((void**)&fb,  g_fb);
    cudaGetSymbolAddress((void**)&flA, g_flA);
    cudaGetSymbolAddress((void**)&flB, g_flB);
    cudaGetSymbolAddress((void**)&cnt, g_cnt);
    float* flow_bufs[2] = {flA, flB};

    cudaMemsetAsync(d_out, 0, (size_t)out_size * sizeof(float));

    const int Cin[4]  = {3, 16, 32, 64};
    const int Cout[4] = {16, 32, 64, 128};
    const int Hin[4]  = {512, 256, 128, 64};

    size_t regOff[4];
    {
        size_t a = 0;
        for (int L = 0; L < 4; L++) {
            regOff[L] = a;
            int ho = Hin[L] / 2;
            a += (size_t)NB * Cout[L] * (ho + 2) * (ho + 2);
        }
    }

    for (int L = 0; L < 4; L++) {
        int ho = Hin[L] / 2, co = Cout[L];
        int nc = NB * co;
        int per = 2 * (ho + 2) + 2 * ho;
        int tot = nc * per;
        zero_border_kernel<<<(tot + 255) / 256, 256>>>(fa + regOff[L], nc, ho, ho);
        zero_border_kernel<<<(tot + 255) / 256, 256>>>(fb + regOff[L], nc, ho, ho);
    }

    size_t off = 0;
    const float* flow_in = flow;

    for (int L = 0; L < 4; L++) {
        const int ci = Cin[L], co = Cout[L], hi = Hin[L], ho = hi / 2;
        const float* wA = (const float*)d_in[2 + 6 * L + 0];
        const float* bA = (const float*)d_in[2 + 6 * L + 1];
        const float* aA = (const float*)d_in[2 + 6 * L + 2];
        const float* wB = (const float*)d_in[2 + 6 * L + 3];
        const float* bB = (const float*)d_in[2 + 6 * L + 4];
        const float* aB = (const float*)d_in[2 + 6 * L + 5];

        const int po = ho + 2;
        const size_t planeO = (size_t)po * po;
        float* faL = fa + regOff[L] + po + 1;
        float* fbL = fb + regOff[L] + po + 1;

        // --- conv_a: stride 2, hi -> ho, ROWS=4 ---
        {
            dim3 blk(32, 8);
            dim3 grd(ho / 32, ho / 32, NB * (co / 4));
            size_t sm = 2 * ci * 9 * sizeof(float2);
            if (L == 0) {
                conv3x3_prelu<2, 4, true><<<grd, blk, sm>>>(
                    img, wA, bA, aA, faL, ci, co, hi, hi,
                    hi, (size_t)hi * hi, po, planeO);
            } else {
                const int pi = hi + 2;
                const float* inL = fb + regOff[L - 1] + pi + 1;
                conv3x3_prelu<2, 4, false><<<grd, blk, sm>>>(
                    inL, wA, bA, aA, faL, ci, co, hi, hi,
                    pi, (size_t)pi * pi, po, planeO);
            }
        }

        // --- conv_b: stride 1 at ho, ROWS=8 (or 4 for ho=32) ---
        {
            dim3 blk(32, 8);
            size_t sm = 2 * co * 9 * sizeof(float2);
            if (ho >= 64) {
                dim3 grd(ho / 32, ho / 64, NB * (co / 4));
                conv3x3_prelu<1, 8, false><<<grd, blk, sm>>>(
                    faL, wB, bB, aB, fbL, co, co, ho, ho,
                    po, planeO, po, planeO);
            } else {
                dim3 grd(ho / 32, ho / 32, NB * (co / 4));
                conv3x3_prelu<1, 4, false><<<grd, blk, sm>>>(
                    faL, wB, bB, aB, fbL, co, co, ho, ho,
                    po, planeO, po, planeO);
            }
        }

        // --- halve flow: hi -> ho ---
        float* fl = flow_bufs[L & 1];
        {
            int nfl = NB * 2 * ho * ho;
            halve_flow_kernel<<<(nfl + 255) / 256, 256>>>(flow_in, fl, ho, ho);
        }

        // --- splat into output region ---
        cudaMemsetAsync(cnt, 0, (size_t)NB * ho * ho * sizeof(float));
        float* numL = out + off;
        {
            int np = NB * ho * ho;
            splat_add_kernel<<<(np + 255) / 256, 256>>>(
                fb + regOff[L], fl, numL, cnt, co, ho, ho);
        }
        {
            int ne = NB * co * ho * ho;
            norm_div_kernel<<<(ne + 255) / 256, 256>>>(numL, cnt, co, ho * ho);
        }

        off += (size_t)NB * co * ho * ho;
        flow_in = fl;
    }
}

// round 5
// speedup vs baseline: 1.2710x; 1.2710x over previous
#include <cuda_runtime.h>
#include <cstddef>

// ---------------------------------------------------------------------------
// ContextNet (RIFE-style) on GB300 — padded buffers, scalar-FFMA conv (best),
// channel-last splat with red.global.add.v4.f32, transpose-divide epilogue.
// Levels: (Cin,Cout,Hin): (3,16,512) (16,32,256) (32,64,128) (64,128,64)
// ---------------------------------------------------------------------------

#define NB 16  // batch

__device__ float g_fa[33000000];   // conv_a output; reused as splat scratch
__device__ float g_fb[33000000];   // conv_b output / next level input
__device__ float g_flA[(size_t)16 * 2 * 256 * 256];
__device__ float g_flB[(size_t)16 * 2 * 256 * 256];
__device__ float g_cnt[(size_t)16 * 256 * 256];

// ---------------------------------------------------------------------------
// Zero the 1-px border of NC padded planes of logical size HxW (pitch W+2).
// ---------------------------------------------------------------------------
__global__ void zero_border_kernel(float* __restrict__ base, int NC, int H, int W) {
    int per = 2 * (W + 2) + 2 * H;
    int idx = blockIdx.x * blockDim.x + threadIdx.x;
    if (idx >= NC * per) return;
    int c = idx / per, r = idx % per;
    float* p = base + (size_t)c * (H + 2) * (W + 2);
    if (r < W + 2) {
        p[r] = 0.f;
    } else if (r < 2 * (W + 2)) {
        p[(size_t)(H + 1) * (W + 2) + (r - (W + 2))] = 0.f;
    } else {
        int rr = r - 2 * (W + 2);
        int y = rr % H;
        bool right = rr >= H;
        p[(size_t)(y + 1) * (W + 2) + (right ? (W + 1) : 0)] = 0.f;
    }
}

// ---------------------------------------------------------------------------
// Direct 3x3 conv + bias + PReLU. 4 output channels x ROWS rows per thread.
// Block (32,8); tile = 32 cols x 8*ROWS rows. (R3 structure — best known.)
// ---------------------------------------------------------------------------
template <int STRIDE, int ROWS, bool PRED>
__global__ void conv3x3_prelu(const float* __restrict__ in,
                              const float* __restrict__ wt,
                              const float* __restrict__ bias,
                              const float* __restrict__ alpha,
                              float* __restrict__ out,
                              int Cin, int Cout, int Hin, int Win,
                              int inPitch, size_t inPlane,
                              int outPitch, size_t outPlane) {
    const int cg = Cout >> 2;
    const int co0 = (blockIdx.z % cg) * 4;
    const int n   = blockIdx.z / cg;

    extern __shared__ float sw[];            // [4][Cin][9]
    const int tid = threadIdx.y * 32 + threadIdx.x;
    const int nw = 4 * Cin * 9;
    const float* wsrc = wt + (size_t)co0 * Cin * 9;
    for (int i = tid; i < nw; i += 256) sw[i] = wsrc[i];
    __syncthreads();

    const int x  = blockIdx.x * 32 + threadIdx.x;
    const int y0 = blockIdx.y * (8 * ROWS) + threadIdx.y * ROWS;

    float acc[4][ROWS];
#pragma unroll
    for (int c = 0; c < 4; c++)
#pragma unroll
        for (int j = 0; j < ROWS; j++) acc[c][j] = 0.f;

    const float* ib = in + (size_t)n * Cin * inPlane;
    constexpr int NR = (STRIDE == 1) ? (ROWS + 2) : (2 * ROWS + 1);

    for (int ci = 0; ci < Cin; ci++) {
        const float* ip = ib + (size_t)ci * inPlane;
        float v[NR][3];
#pragma unroll
        for (int r = 0; r < NR; r++) {
            const int iy = STRIDE * y0 - 1 + r;
            const float* rp = ip + (ptrdiff_t)iy * inPitch + (STRIDE * x - 1);
            if (PRED) {
                bool yok = ((unsigned)iy < (unsigned)Hin);
#pragma unroll
                for (int c = 0; c < 3; c++) {
                    int ix = STRIDE * x - 1 + c;
                    v[r][c] = (yok && (unsigned)ix < (unsigned)Win) ? rp[c] : 0.f;
                }
            } else {
#pragma unroll
                for (int c = 0; c < 3; c++) v[r][c] = rp[c];
            }
        }
#pragma unroll
        for (int c4 = 0; c4 < 4; c4++) {
            const float* w9 = sw + (c4 * Cin + ci) * 9;
            float w[9];
#pragma unroll
            for (int k = 0; k < 9; k++) w[k] = w9[k];
#pragma unroll
            for (int j = 0; j < ROWS; j++)
#pragma unroll
                for (int ky = 0; ky < 3; ky++)
#pragma unroll
                    for (int kx = 0; kx < 3; kx++)
                        acc[c4][j] = fmaf(v[STRIDE * j + ky][kx], w[ky * 3 + kx], acc[c4][j]);
        }
    }

#pragma unroll
    for (int c4 = 0; c4 < 4; c4++) {
        const int co = co0 + c4;
        const float bv = bias[co];
        const float av = alpha[co];
        float* ob = out + (size_t)(n * Cout + co) * outPlane;
#pragma unroll
        for (int j = 0; j < ROWS; j++) {
            float o = acc[c4][j] + bv;
            o = (o >= 0.f) ? o : av * o;
            ob[(size_t)(y0 + j) * outPitch + x] = o;
        }
    }
}

// ---------------------------------------------------------------------------
// Flow halving: 2x2 mean * 0.5 == sum * 0.125
// ---------------------------------------------------------------------------
__global__ void halve_flow_kernel(const float* __restrict__ in,
                                  float* __restrict__ out, int Hout, int Wout) {
    int idx = blockIdx.x * blockDim.x + threadIdx.x;
    int total = NB * 2 * Hout * Wout;
    if (idx >= total) return;
    int w = idx % Wout;
    int h = (idx / Wout) % Hout;
    int nc = idx / (Wout * Hout);
    int Win = 2 * Wout;
    const float* ip = in + (size_t)nc * (4 * Hout * Wout);
    const float* r0 = ip + (2 * h) * Win + 2 * w;
    const float* r1 = r0 + Win;
    out[idx] = (r0[0] + r0[1] + r1[0] + r1[1]) * 0.125f;
}

// ---- vectorized global reduction (fp32 x4) --------------------------------
__device__ __forceinline__ void red_add_v4(float* p, float a, float b,
                                           float c, float d) {
    asm volatile("red.global.add.v4.f32 [%0], {%1, %2, %3, %4};"
                 :: "l"(p), "f"(a), "f"(b), "f"(c), "f"(d) : "memory");
}

// ---------------------------------------------------------------------------
// Forward bilinear splat into CHANNEL-LAST scratch [n][p][c] via red.v4.
// feat is padded planar (pitch W+2). cnt planar [n][p].
// ---------------------------------------------------------------------------
__global__ void splat_add_cl(const float* __restrict__ feat,
                             const float* __restrict__ flow,
                             float* __restrict__ scr,
                             float* __restrict__ cnt,
                             int C, int H, int W) {
    int idx = blockIdx.x * blockDim.x + threadIdx.x;
    int HW = H * W;
    int total = NB * HW;
    if (idx >= total) return;
    int n = idx / HW;
    int p = idx % HW;
    int y = p / W;
    int x = p % W;

    const float* fb = flow + (size_t)n * 2 * HW;
    float fx = fb[p] + (float)x;
    float fy = fb[HW + p] + (float)y;

    float x0f = floorf(fx), y0f = floorf(fy);
    int ix0 = (int)x0f, iy0 = (int)y0f;
    float wx1 = fx - x0f, wy1 = fy - y0f;
    float wx0 = 1.f - wx1, wy0 = 1.f - wy1;

    int   xi[4] = {ix0, ix0 + 1, ix0,     ix0 + 1};
    int   yi[4] = {iy0, iy0,     iy0 + 1, iy0 + 1};
    float wv[4] = {wx0 * wy0, wx1 * wy0, wx0 * wy1, wx1 * wy1};
    int   tgt[4];
    bool  ok[4];
#pragma unroll
    for (int k = 0; k < 4; k++) {
        ok[k] = ((unsigned)xi[k] < (unsigned)W) && ((unsigned)yi[k] < (unsigned)H);
        tgt[k] = yi[k] * W + xi[k];
        if (ok[k]) atomicAdd(&cnt[n * HW + tgt[k]], wv[k]);
    }

    const size_t plane = (size_t)(H + 2) * (W + 2);
    const float* src = feat + (size_t)n * C * plane + (size_t)(y + 1) * (W + 2) + (x + 1);
    float* sb = scr + (size_t)n * HW * C;

    for (int c0 = 0; c0 < C; c0 += 4) {
        float s0 = src[(size_t)(c0 + 0) * plane];
        float s1 = src[(size_t)(c0 + 1) * plane];
        float s2 = src[(size_t)(c0 + 2) * plane];
        float s3 = src[(size_t)(c0 + 3) * plane];
#pragma unroll
        for (int k = 0; k < 4; k++) {
            if (ok[k]) {
                float w = wv[k];
                red_add_v4(sb + (size_t)tgt[k] * C + c0,
                           s0 * w, s1 * w, s2 * w, s3 * w);
            }
        }
    }
}

// ---------------------------------------------------------------------------
// Transpose channel-last scratch [n][p][c] -> NCHW out, dividing by count.
// Block (32,8); tile 32 pixels x 32 channels via smem.
// ---------------------------------------------------------------------------
__global__ void norm_transpose(const float* __restrict__ scr,
                               const float* __restrict__ cnt,
                               float* __restrict__ out,
                               int C, int HW) {
    __shared__ float tile[32][33];
    const int n  = blockIdx.z;
    const int p0 = blockIdx.x * 32;
    const int c0 = blockIdx.y * 32;
    const int tx = threadIdx.x, ty = threadIdx.y;

    const float* sb = scr + (size_t)n * HW * C;
    const int c = c0 + tx;
#pragma unroll
    for (int r = 0; r < 4; r++) {
        int pl = ty + 8 * r;
        if (c < C)
            tile[pl][tx] = sb[(size_t)(p0 + pl) * C + c];
    }
    __syncthreads();

    float cv = cnt[(size_t)n * HW + p0 + tx];
    float inv = 1.f / ((cv == 0.f) ? 1.f : cv);
#pragma unroll
    for (int r = 0; r < 4; r++) {
        int cc = c0 + ty + 8 * r;
        if (cc < C)
            out[((size_t)n * C + cc) * HW + p0 + tx] = tile[tx][ty + 8 * r] * inv;
    }
}

// ---------------------------------------------------------------------------
// Host launcher
// ---------------------------------------------------------------------------
extern "C" void kernel_launch(void* const* d_in, const int* in_sizes, int n_in,
                              void* d_out, int out_size) {
    const float* img  = (const float*)d_in[0];
    const float* flow = (const float*)d_in[1];
    float* out = (float*)d_out;

    float *fa, *fb, *flA, *flB, *cnt;
    cudaGetSymbolAddress((void**)&fa,  g_fa);
    cudaGetSymbolAddress((void**)&fb,  g_fb);
    cudaGetSymbolAddress((void**)&flA, g_flA);
    cudaGetSymbolAddress((void**)&flB, g_flB);
    cudaGetSymbolAddress((void**)&cnt, g_cnt);
    float* flow_bufs[2] = {flA, flB};

    const int Cin[4]  = {3, 16, 32, 64};
    const int Cout[4] = {16, 32, 64, 128};
    const int Hin[4]  = {512, 256, 128, 64};

    size_t regOff[4];
    {
        size_t a = 0;
        for (int L = 0; L < 4; L++) {
            regOff[L] = a;
            int ho = Hin[L] / 2;
            a += (size_t)NB * Cout[L] * (ho + 2) * (ho + 2);
        }
    }

    size_t off = 0;
    const float* flow_in = flow;

    for (int L = 0; L < 4; L++) {
        const int ci = Cin[L], co = Cout[L], hi = Hin[L], ho = hi / 2;
        const float* wA = (const float*)d_in[2 + 6 * L + 0];
        const float* bA = (const float*)d_in[2 + 6 * L + 1];
        const float* aA = (const float*)d_in[2 + 6 * L + 2];
        const float* wB = (const float*)d_in[2 + 6 * L + 3];
        const float* bB = (const float*)d_in[2 + 6 * L + 4];
        const float* aB = (const float*)d_in[2 + 6 * L + 5];

        const int po = ho + 2;
        const size_t planeO = (size_t)po * po;
        float* faL = fa + regOff[L] + po + 1;
        float* fbL = fb + regOff[L] + po + 1;

        // zero halos for this level's two buffers (before the convs that read them)
        {
            int nc = NB * co;
            int per = 2 * (ho + 2) + 2 * ho;
            int tot = nc * per;
            zero_border_kernel<<<(tot + 255) / 256, 256>>>(fa + regOff[L], nc, ho, ho);
            zero_border_kernel<<<(tot + 255) / 256, 256>>>(fb + regOff[L], nc, ho, ho);
        }

        // --- conv_a: stride 2, hi -> ho, ROWS=4 ---
        {
            dim3 blk(32, 8);
            dim3 grd(ho / 32, ho / 32, NB * (co / 4));
            size_t sm = 4 * ci * 9 * sizeof(float);
            if (L == 0) {
                conv3x3_prelu<2, 4, true><<<grd, blk, sm>>>(
                    img, wA, bA, aA, faL, ci, co, hi, hi,
                    hi, (size_t)hi * hi, po, planeO);
            } else {
                const int pi = hi + 2;
                const float* inL = fb + regOff[L - 1] + pi + 1;
                conv3x3_prelu<2, 4, false><<<grd, blk, sm>>>(
                    inL, wA, bA, aA, faL, ci, co, hi, hi,
                    pi, (size_t)pi * pi, po, planeO);
            }
        }

        // --- conv_b: stride 1 at ho, ROWS=8 (or 4 for ho=32) ---
        {
            dim3 blk(32, 8);
            size_t sm = 4 * co * 9 * sizeof(float);
            if (ho >= 64) {
                dim3 grd(ho / 32, ho / 64, NB * (co / 4));
                conv3x3_prelu<1, 8, false><<<grd, blk, sm>>>(
                    faL, wB, bB, aB, fbL, co, co, ho, ho,
                    po, planeO, po, planeO);
            } else {
                dim3 grd(ho / 32, ho / 32, NB * (co / 4));
                conv3x3_prelu<1, 4, false><<<grd, blk, sm>>>(
                    faL, wB, bB, aB, fbL, co, co, ho, ho,
                    po, planeO, po, planeO);
            }
        }

        // --- halve flow: hi -> ho ---
        float* fl = flow_bufs[L & 1];
        {
            int nfl = NB * 2 * ho * ho;
            halve_flow_kernel<<<(nfl + 255) / 256, 256>>>(flow_in, fl, ho, ho);
        }

        // --- splat into channel-last scratch (reuse fa region; conv_b done) ---
        float* scr = fa + regOff[L];
        cudaMemsetAsync(scr, 0, (size_t)NB * co * ho * ho * sizeof(float));
        cudaMemsetAsync(cnt, 0, (size_t)NB * ho * ho * sizeof(float));
        {
            int np = NB * ho * ho;
            splat_add_cl<<<(np + 255) / 256, 256>>>(
                fb + regOff[L], fl, scr, cnt, co, ho, ho);
        }

        // --- transpose + divide into NCHW output ---
        {
            int HW = ho * ho;
            dim3 blk(32, 8);
            dim3 grd(HW / 32, (co + 31) / 32, NB);
            norm_transpose<<<grd, blk>>>(scr, cnt, out + off, co, HW);
        }

        off += (size_t)NB * co * ho * ho;
        flow_in = fl;
    }
}

// round 6
// speedup vs baseline: 1.3067x; 1.0281x over previous
#include <cuda_runtime.h>
#include <cstddef>

// ---------------------------------------------------------------------------
// ContextNet (RIFE-style) on GB300 — padded buffers, scalar-FFMA conv,
// splat FUSED into conv_b epilogue (channel-last red.v4), transpose-divide.
// Levels: (Cin,Cout,Hin): (3,16,512) (16,32,256) (32,64,128) (64,128,64)
// ---------------------------------------------------------------------------

#define NB 16  // batch

__device__ float g_fa[33000000];                       // conv_a outputs (padded)
__device__ float g_fb[33000000];                       // conv_b outputs (padded)
__device__ float g_scr[(size_t)16 * 16 * 256 * 256];   // channel-last splat scratch
__device__ float g_flA[(size_t)16 * 2 * 256 * 256];
__device__ float g_flB[(size_t)16 * 2 * 256 * 256];
__device__ float g_cnt[(size_t)16 * 256 * 256];

// ---- vectorized global reduction (fp32 x4) --------------------------------
__device__ __forceinline__ void red_add_v4(float* p, float a, float b,
                                           float c, float d) {
    asm volatile("red.global.add.v4.f32 [%0], {%1, %2, %3, %4};"
                 :: "l"(p), "f"(a), "f"(b), "f"(c), "f"(d) : "memory");
}

// ---------------------------------------------------------------------------
// Zero the 1-px border of NC padded planes of logical size HxW (pitch W+2).
// ---------------------------------------------------------------------------
__global__ void zero_border_kernel(float* __restrict__ base, int NC, int H, int W) {
    int per = 2 * (W + 2) + 2 * H;
    int idx = blockIdx.x * blockDim.x + threadIdx.x;
    if (idx >= NC * per) return;
    int c = idx / per, r = idx % per;
    float* p = base + (size_t)c * (H + 2) * (W + 2);
    if (r < W + 2) {
        p[r] = 0.f;
    } else if (r < 2 * (W + 2)) {
        p[(size_t)(H + 1) * (W + 2) + (r - (W + 2))] = 0.f;
    } else {
        int rr = r - 2 * (W + 2);
        int y = rr % H;
        bool right = rr >= H;
        p[(size_t)(y + 1) * (W + 2) + (right ? (W + 1) : 0)] = 0.f;
    }
}

// ---------------------------------------------------------------------------
// 3x3 conv + bias + PReLU; 4 co x ROWS rows per thread. Optional fused
// forward-splat epilogue (SPLAT): channel-last red.v4 into scr, cnt atomics
// from the co0==0 blocks.
// ---------------------------------------------------------------------------
template <int STRIDE, int ROWS, bool PRED, bool SPLAT>
__global__ void conv3x3_prelu(const float* __restrict__ in,
                              const float* __restrict__ wt,
                              const float* __restrict__ bias,
                              const float* __restrict__ alpha,
                              float* __restrict__ out,
                              int Cin, int Cout, int Hin, int Win,
                              int inPitch, size_t inPlane,
                              int outPitch, size_t outPlane,
                              const float* __restrict__ flw,
                              float* __restrict__ scr,
                              float* __restrict__ cnt) {
    const int cg = Cout >> 2;
    const int co0 = (blockIdx.z % cg) * 4;
    const int n   = blockIdx.z / cg;

    extern __shared__ float sw[];            // [4][Cin][9]
    const int tid = threadIdx.y * 32 + threadIdx.x;
    const int nw = 4 * Cin * 9;
    const float* wsrc = wt + (size_t)co0 * Cin * 9;
    for (int i = tid; i < nw; i += 256) sw[i] = wsrc[i];
    __syncthreads();

    const int x  = blockIdx.x * 32 + threadIdx.x;
    const int y0 = blockIdx.y * (8 * ROWS) + threadIdx.y * ROWS;

    float acc[4][ROWS];
#pragma unroll
    for (int c = 0; c < 4; c++)
#pragma unroll
        for (int j = 0; j < ROWS; j++) acc[c][j] = 0.f;

    const float* ib = in + (size_t)n * Cin * inPlane;
    constexpr int NR = (STRIDE == 1) ? (ROWS + 2) : (2 * ROWS + 1);

    for (int ci = 0; ci < Cin; ci++) {
        const float* ip = ib + (size_t)ci * inPlane;
        float v[NR][3];
#pragma unroll
        for (int r = 0; r < NR; r++) {
            const int iy = STRIDE * y0 - 1 + r;
            const float* rp = ip + (ptrdiff_t)iy * inPitch + (STRIDE * x - 1);
            if (PRED) {
                bool yok = ((unsigned)iy < (unsigned)Hin);
#pragma unroll
                for (int c = 0; c < 3; c++) {
                    int ix = STRIDE * x - 1 + c;
                    v[r][c] = (yok && (unsigned)ix < (unsigned)Win) ? rp[c] : 0.f;
                }
            } else {
#pragma unroll
                for (int c = 0; c < 3; c++) v[r][c] = rp[c];
            }
        }
#pragma unroll
        for (int c4 = 0; c4 < 4; c4++) {
            const float* w9 = sw + (c4 * Cin + ci) * 9;
            float w[9];
#pragma unroll
            for (int k = 0; k < 9; k++) w[k] = w9[k];
#pragma unroll
            for (int j = 0; j < ROWS; j++)
#pragma unroll
                for (int ky = 0; ky < 3; ky++)
#pragma unroll
                    for (int kx = 0; kx < 3; kx++)
                        acc[c4][j] = fmaf(v[STRIDE * j + ky][kx], w[ky * 3 + kx], acc[c4][j]);
        }
    }

    // bias + PReLU (in place), write padded NCHW output
#pragma unroll
    for (int c4 = 0; c4 < 4; c4++) {
        const int co = co0 + c4;
        const float bv = bias[co];
        const float av = alpha[co];
        float* ob = out + (size_t)(n * Cout + co) * outPlane;
#pragma unroll
        for (int j = 0; j < ROWS; j++) {
            float o = acc[c4][j] + bv;
            o = (o >= 0.f) ? o : av * o;
            acc[c4][j] = o;
            ob[(size_t)(y0 + j) * outPitch + x] = o;
        }
    }

    if (SPLAT) {
        const int W = Win / STRIDE;          // == Hout == Wout
        const int HW = W * W;
        const float* fp = flw + (size_t)n * 2 * HW;
        float* sb = scr + (size_t)n * HW * Cout + co0;
#pragma unroll
        for (int j = 0; j < ROWS; j++) {
            const int yy = y0 + j;
            const int p = yy * W + x;
            float fx = fp[p] + (float)x;
            float fy = fp[HW + p] + (float)yy;
            float x0f = floorf(fx), y0f = floorf(fy);
            int ix0 = (int)x0f, iy0 = (int)y0f;
            float wx1 = fx - x0f, wy1 = fy - y0f;
            float wx0 = 1.f - wx1, wy0 = 1.f - wy1;
            int   xi[4] = {ix0, ix0 + 1, ix0,     ix0 + 1};
            int   yi[4] = {iy0, iy0,     iy0 + 1, iy0 + 1};
            float wv[4] = {wx0 * wy0, wx1 * wy0, wx0 * wy1, wx1 * wy1};
            float s0 = acc[0][j], s1 = acc[1][j], s2 = acc[2][j], s3 = acc[3][j];
#pragma unroll
            for (int k = 0; k < 4; k++) {
                bool ok = ((unsigned)xi[k] < (unsigned)W) &&
                          ((unsigned)yi[k] < (unsigned)W);
                if (ok) {
                    int tgt = yi[k] * W + xi[k];
                    float w = wv[k];
                    red_add_v4(sb + (size_t)tgt * Cout,
                               s0 * w, s1 * w, s2 * w, s3 * w);
                    if (co0 == 0)
                        atomicAdd(&cnt[(size_t)n * HW + tgt], w);
                }
            }
        }
    }
}

// ---------------------------------------------------------------------------
// Flow halving: 2x2 mean * 0.5 == sum * 0.125
// ---------------------------------------------------------------------------
__global__ void halve_flow_kernel(const float* __restrict__ in,
                                  float* __restrict__ out, int Hout, int Wout) {
    int idx = blockIdx.x * blockDim.x + threadIdx.x;
    int total = NB * 2 * Hout * Wout;
    if (idx >= total) return;
    int w = idx % Wout;
    int h = (idx / Wout) % Hout;
    int nc = idx / (Wout * Hout);
    int Win = 2 * Wout;
    const float* ip = in + (size_t)nc * (4 * Hout * Wout);
    const float* r0 = ip + (2 * h) * Win + 2 * w;
    const float* r1 = r0 + Win;
    out[idx] = (r0[0] + r0[1] + r1[0] + r1[1]) * 0.125f;
}

// ---------------------------------------------------------------------------
// Transpose channel-last scratch [n][p][c] -> NCHW out, dividing by count.
// ---------------------------------------------------------------------------
__global__ void norm_transpose(const float* __restrict__ scr,
                               const float* __restrict__ cnt,
                               float* __restrict__ out,
                               int C, int HW) {
    __shared__ float tile[32][33];
    const int n  = blockIdx.z;
    const int p0 = blockIdx.x * 32;
    const int c0 = blockIdx.y * 32;
    const int tx = threadIdx.x, ty = threadIdx.y;

    const float* sb = scr + (size_t)n * HW * C;
    const int c = c0 + tx;
#pragma unroll
    for (int r = 0; r < 4; r++) {
        int pl = ty + 8 * r;
        if (c < C)
            tile[pl][tx] = sb[(size_t)(p0 + pl) * C + c];
    }
    __syncthreads();

    float cv = cnt[(size_t)n * HW + p0 + tx];
    float inv = 1.f / ((cv == 0.f) ? 1.f : cv);
#pragma unroll
    for (int r = 0; r < 4; r++) {
        int cc = c0 + ty + 8 * r;
        if (cc < C)
            out[((size_t)n * C + cc) * HW + p0 + tx] = tile[tx][ty + 8 * r] * inv;
    }
}

// ---------------------------------------------------------------------------
// Host launcher
// ---------------------------------------------------------------------------
extern "C" void kernel_launch(void* const* d_in, const int* in_sizes, int n_in,
                              void* d_out, int out_size) {
    const float* img  = (const float*)d_in[0];
    const float* flow = (const float*)d_in[1];
    float* out = (float*)d_out;

    float *fa, *fb, *scr, *flA, *flB, *cnt;
    cudaGetSymbolAddress((void**)&fa,  g_fa);
    cudaGetSymbolAddress((void**)&fb,  g_fb);
    cudaGetSymbolAddress((void**)&scr, g_scr);
    cudaGetSymbolAddress((void**)&flA, g_flA);
    cudaGetSymbolAddress((void**)&flB, g_flB);
    cudaGetSymbolAddress((void**)&cnt, g_cnt);
    float* flow_bufs[2] = {flA, flB};

    const int Cin[4]  = {3, 16, 32, 64};
    const int Cout[4] = {16, 32, 64, 128};
    const int Hin[4]  = {512, 256, 128, 64};

    size_t regOff[4];
    {
        size_t a = 0;
        for (int L = 0; L < 4; L++) {
            regOff[L] = a;
            int ho = Hin[L] / 2;
            a += (size_t)NB * Cout[L] * (ho + 2) * (ho + 2);
        }
    }

    size_t off = 0;
    const float* flow_in = flow;

    for (int L = 0; L < 4; L++) {
        const int ci = Cin[L], co = Cout[L], hi = Hin[L], ho = hi / 2;
        const float* wA = (const float*)d_in[2 + 6 * L + 0];
        const float* bA = (const float*)d_in[2 + 6 * L + 1];
        const float* aA = (const float*)d_in[2 + 6 * L + 2];
        const float* wB = (const float*)d_in[2 + 6 * L + 3];
        const float* bB = (const float*)d_in[2 + 6 * L + 4];
        const float* aB = (const float*)d_in[2 + 6 * L + 5];

        const int po = ho + 2;
        const size_t planeO = (size_t)po * po;
        float* faL = fa + regOff[L] + po + 1;
        float* fbL = fb + regOff[L] + po + 1;

        // zero halos: fa always (conv_b reads it); fb only if next level reads it
        {
            int nc = NB * co;
            int per = 2 * (ho + 2) + 2 * ho;
            int tot = nc * per;
            zero_border_kernel<<<(tot + 255) / 256, 256>>>(fa + regOff[L], nc, ho, ho);
            if (L < 3)
                zero_border_kernel<<<(tot + 255) / 256, 256>>>(fb + regOff[L], nc, ho, ho);
        }

        // --- conv_a: stride 2, hi -> ho, ROWS=4, no splat ---
        {
            dim3 blk(32, 8);
            dim3 grd(ho / 32, ho / 32, NB * (co / 4));
            size_t sm = 4 * ci * 9 * sizeof(float);
            if (L == 0) {
                conv3x3_prelu<2, 4, true, false><<<grd, blk, sm>>>(
                    img, wA, bA, aA, faL, ci, co, hi, hi,
                    hi, (size_t)hi * hi, po, planeO, nullptr, nullptr, nullptr);
            } else {
                const int pi = hi + 2;
                const float* inL = fb + regOff[L - 1] + pi + 1;
                conv3x3_prelu<2, 4, false, false><<<grd, blk, sm>>>(
                    inL, wA, bA, aA, faL, ci, co, hi, hi,
                    pi, (size_t)pi * pi, po, planeO, nullptr, nullptr, nullptr);
            }
        }

        // --- halve flow: hi -> ho (before fused conv_b) ---
        float* fl = flow_bufs[L & 1];
        {
            int nfl = NB * 2 * ho * ho;
            halve_flow_kernel<<<(nfl + 255) / 256, 256>>>(flow_in, fl, ho, ho);
        }

        // --- zero splat accumulators ---
        cudaMemsetAsync(scr, 0, (size_t)NB * co * ho * ho * sizeof(float));
        cudaMemsetAsync(cnt, 0, (size_t)NB * ho * ho * sizeof(float));

        // --- conv_b: stride 1 at ho, fused splat epilogue ---
        {
            dim3 blk(32, 8);
            size_t sm = 4 * co * 9 * sizeof(float);
            if (ho >= 64) {
                dim3 grd(ho / 32, ho / 64, NB * (co / 4));
                conv3x3_prelu<1, 8, false, true><<<grd, blk, sm>>>(
                    faL, wB, bB, aB, fbL, co, co, ho, ho,
                    po, planeO, po, planeO, fl, scr, cnt);
            } else {
                dim3 grd(ho / 32, ho / 32, NB * (co / 4));
                conv3x3_prelu<1, 4, false, true><<<grd, blk, sm>>>(
                    faL, wB, bB, aB, fbL, co, co, ho, ho,
                    po, planeO, po, planeO, fl, scr, cnt);
            }
        }

        // --- transpose + divide into NCHW output ---
        {
            int HW = ho * ho;
            dim3 blk(32, 8);
            dim3 grd(HW / 32, (co + 31) / 32, NB);
            norm_transpose<<<grd, blk>>>(scr, cnt, out + off, co, HW);
        }

        off += (size_t)NB * co * ho * ho;
        flow_in = fl;
    }
}

// round 7
// speedup vs baseline: 1.3300x; 1.0178x over previous
#include <cuda_runtime.h>
#include <cstddef>

// ---------------------------------------------------------------------------
// ContextNet (RIFE-style) on GB300 — padded buffers, scalar-FFMA conv,
// fused conv_b+splat, two-stream overlap, merged border zeroing.
// Levels: (Cin,Cout,Hin): (3,16,512) (16,32,256) (32,64,128) (64,128,64)
// ---------------------------------------------------------------------------

#define NB 16  // batch

__device__ float g_fa[33000000];                       // conv_a outputs (padded)
__device__ float g_fb[33000000];                       // conv_b outputs (padded)
__device__ float g_scrA[(size_t)16 * 16 * 256 * 256];  // channel-last splat scratch (ping)
__device__ float g_scrB[(size_t)16 * 16 * 256 * 256];  // (pong)
__device__ float g_cntA[(size_t)16 * 256 * 256];
__device__ float g_cntB[(size_t)16 * 256 * 256];
__device__ float g_fl[3000000];                        // all 4 halved flows

// ---- vectorized global reduction (fp32 x4) --------------------------------
__device__ __forceinline__ void red_add_v4(float* p, float a, float b,
                                           float c, float d) {
    asm volatile("red.global.add.v4.f32 [%0], {%1, %2, %3, %4};"
                 :: "l"(p), "f"(a), "f"(b), "f"(c), "f"(d) : "memory");
}

// ---------------------------------------------------------------------------
// Merged border zeroing: blockIdx.y selects one of up to 8 jobs.
// ---------------------------------------------------------------------------
struct BorderJobs {
    int    sel[8];    // 0 = fa, 1 = fb
    long long off[8];
    int    NC[8];
    int    H[8];
    int    njobs;
};

__global__ void zero_borders_all(float* __restrict__ fa, float* __restrict__ fb,
                                 BorderJobs J) {
    int j = blockIdx.y;
    if (j >= J.njobs) return;
    int H = J.H[j], NC = J.NC[j];
    int W = H;
    int per = 2 * (W + 2) + 2 * H;
    int idx = blockIdx.x * blockDim.x + threadIdx.x;
    if (idx >= NC * per) return;
    int c = idx / per, r = idx % per;
    float* p = (J.sel[j] ? fb : fa) + J.off[j] + (size_t)c * (H + 2) * (W + 2);
    if (r < W + 2) {
        p[r] = 0.f;
    } else if (r < 2 * (W + 2)) {
        p[(size_t)(H + 1) * (W + 2) + (r - (W + 2))] = 0.f;
    } else {
        int rr = r - 2 * (W + 2);
        int y = rr % H;
        bool right = rr >= H;
        p[(size_t)(y + 1) * (W + 2) + (right ? (W + 1) : 0)] = 0.f;
    }
}

// ---------------------------------------------------------------------------
// 3x3 conv + bias + PReLU; 4 co x ROWS rows per thread. Optional fused
// forward-splat epilogue. MINB: min blocks/SM for launch_bounds.
// ---------------------------------------------------------------------------
template <int STRIDE, int ROWS, bool PRED, bool SPLAT, int MINB>
__global__ void __launch_bounds__(256, MINB)
conv3x3_prelu(const float* __restrict__ in,
              const float* __restrict__ wt,
              const float* __restrict__ bias,
              const float* __restrict__ alpha,
              float* __restrict__ out,
              int Cin, int Cout, int Hin, int Win,
              int inPitch, size_t inPlane,
              int outPitch, size_t outPlane,
              const float* __restrict__ flw,
              float* __restrict__ scr,
              float* __restrict__ cnt) {
    const int cg = Cout >> 2;
    const int co0 = (blockIdx.z % cg) * 4;
    const int n   = blockIdx.z / cg;

    extern __shared__ float sw[];            // [4][Cin][9]
    const int tid = threadIdx.y * 32 + threadIdx.x;
    const int nw = 4 * Cin * 9;
    const float* wsrc = wt + (size_t)co0 * Cin * 9;
    for (int i = tid; i < nw; i += 256) sw[i] = wsrc[i];
    __syncthreads();

    const int x  = blockIdx.x * 32 + threadIdx.x;
    const int y0 = blockIdx.y * (8 * ROWS) + threadIdx.y * ROWS;

    float acc[4][ROWS];
#pragma unroll
    for (int c = 0; c < 4; c++)
#pragma unroll
        for (int j = 0; j < ROWS; j++) acc[c][j] = 0.f;

    const float* ib = in + (size_t)n * Cin * inPlane;
    constexpr int NR = (STRIDE == 1) ? (ROWS + 2) : (2 * ROWS + 1);

    for (int ci = 0; ci < Cin; ci++) {
        const float* ip = ib + (size_t)ci * inPlane;
        float v[NR][3];
#pragma unroll
        for (int r = 0; r < NR; r++) {
            const int iy = STRIDE * y0 - 1 + r;
            const float* rp = ip + (ptrdiff_t)iy * inPitch + (STRIDE * x - 1);
            if (PRED) {
                bool yok = ((unsigned)iy < (unsigned)Hin);
#pragma unroll
                for (int c = 0; c < 3; c++) {
                    int ix = STRIDE * x - 1 + c;
                    v[r][c] = (yok && (unsigned)ix < (unsigned)Win) ? rp[c] : 0.f;
                }
            } else {
#pragma unroll
                for (int c = 0; c < 3; c++) v[r][c] = rp[c];
            }
        }
#pragma unroll
        for (int c4 = 0; c4 < 4; c4++) {
            const float* w9 = sw + (c4 * Cin + ci) * 9;
            float w[9];
#pragma unroll
            for (int k = 0; k < 9; k++) w[k] = w9[k];
#pragma unroll
            for (int j = 0; j < ROWS; j++)
#pragma unroll
                for (int ky = 0; ky < 3; ky++)
#pragma unroll
                    for (int kx = 0; kx < 3; kx++)
                        acc[c4][j] = fmaf(v[STRIDE * j + ky][kx], w[ky * 3 + kx], acc[c4][j]);
        }
    }

#pragma unroll
    for (int c4 = 0; c4 < 4; c4++) {
        const int co = co0 + c4;
        const float bv = bias[co];
        const float av = alpha[co];
        float* ob = out + (size_t)(n * Cout + co) * outPlane;
#pragma unroll
        for (int j = 0; j < ROWS; j++) {
            float o = acc[c4][j] + bv;
            o = (o >= 0.f) ? o : av * o;
            acc[c4][j] = o;
            ob[(size_t)(y0 + j) * outPitch + x] = o;
        }
    }

    if (SPLAT) {
        const int W = Win / STRIDE;          // == Hout == Wout
        const int HW = W * W;
        const float* fp = flw + (size_t)n * 2 * HW;
        float* sb = scr + (size_t)n * HW * Cout + co0;
#pragma unroll
        for (int j = 0; j < ROWS; j++) {
            const int yy = y0 + j;
            const int p = yy * W + x;
            float fx = fp[p] + (float)x;
            float fy = fp[HW + p] + (float)yy;
            float x0f = floorf(fx), y0f = floorf(fy);
            int ix0 = (int)x0f, iy0 = (int)y0f;
            float wx1 = fx - x0f, wy1 = fy - y0f;
            float wx0 = 1.f - wx1, wy0 = 1.f - wy1;
            int   xi[4] = {ix0, ix0 + 1, ix0,     ix0 + 1};
            int   yi[4] = {iy0, iy0,     iy0 + 1, iy0 + 1};
            float wv[4] = {wx0 * wy0, wx1 * wy0, wx0 * wy1, wx1 * wy1};
            float s0 = acc[0][j], s1 = acc[1][j], s2 = acc[2][j], s3 = acc[3][j];
#pragma unroll
            for (int k = 0; k < 4; k++) {
                bool ok = ((unsigned)xi[k] < (unsigned)W) &&
                          ((unsigned)yi[k] < (unsigned)W);
                if (ok) {
                    int tgt = yi[k] * W + xi[k];
                    float w = wv[k];
                    red_add_v4(sb + (size_t)tgt * Cout,
                               s0 * w, s1 * w, s2 * w, s3 * w);
                    if (co0 == 0)
                        atomicAdd(&cnt[(size_t)n * HW + tgt], w);
                }
            }
        }
    }
}

// ---------------------------------------------------------------------------
// Flow halving: 2x2 mean * 0.5 == sum * 0.125
// ---------------------------------------------------------------------------
__global__ void halve_flow_kernel(const float* __restrict__ in,
                                  float* __restrict__ out, int Hout, int Wout) {
    int idx = blockIdx.x * blockDim.x + threadIdx.x;
    int total = NB * 2 * Hout * Wout;
    if (idx >= total) return;
    int w = idx % Wout;
    int h = (idx / Wout) % Hout;
    int nc = idx / (Wout * Hout);
    int Win = 2 * Wout;
    const float* ip = in + (size_t)nc * (4 * Hout * Wout);
    const float* r0 = ip + (2 * h) * Win + 2 * w;
    const float* r1 = r0 + Win;
    out[idx] = (r0[0] + r0[1] + r1[0] + r1[1]) * 0.125f;
}

// ---------------------------------------------------------------------------
// Transpose channel-last scratch [n][p][c] -> NCHW out, dividing by count.
// ---------------------------------------------------------------------------
__global__ void norm_transpose(const float* __restrict__ scr,
                               const float* __restrict__ cnt,
                               float* __restrict__ out,
                               int C, int HW) {
    __shared__ float tile[32][33];
    const int n  = blockIdx.z;
    const int p0 = blockIdx.x * 32;
    const int c0 = blockIdx.y * 32;
    const int tx = threadIdx.x, ty = threadIdx.y;

    const float* sb = scr + (size_t)n * HW * C;
    const int c = c0 + tx;
#pragma unroll
    for (int r = 0; r < 4; r++) {
        int pl = ty + 8 * r;
        if (c < C)
            tile[pl][tx] = sb[(size_t)(p0 + pl) * C + c];
    }
    __syncthreads();

    float cv = cnt[(size_t)n * HW + p0 + tx];
    float inv = 1.f / ((cv == 0.f) ? 1.f : cv);
#pragma unroll
    for (int r = 0; r < 4; r++) {
        int cc = c0 + ty + 8 * r;
        if (cc < C)
            out[((size_t)n * C + cc) * HW + p0 + tx] = tile[tx][ty + 8 * r] * inv;
    }
}

// ---------------------------------------------------------------------------
// Host launcher — two-stream overlapped pipeline (graph-capturable).
// ---------------------------------------------------------------------------
extern "C" void kernel_launch(void* const* d_in, const int* in_sizes, int n_in,
                              void* d_out, int out_size) {
    const float* img  = (const float*)d_in[0];
    const float* flow = (const float*)d_in[1];
    float* out = (float*)d_out;

    static cudaStream_t s2 = nullptr;
    static cudaEvent_t evFork, evJoin, evPre[4], evB[4];
    if (!s2) {
        cudaStreamCreateWithFlags(&s2, cudaStreamNonBlocking);
        cudaEventCreateWithFlags(&evFork, cudaEventDisableTiming);
        cudaEventCreateWithFlags(&evJoin, cudaEventDisableTiming);
        for (int i = 0; i < 4; i++) {
            cudaEventCreateWithFlags(&evPre[i], cudaEventDisableTiming);
            cudaEventCreateWithFlags(&evB[i],  cudaEventDisableTiming);
        }
    }

    float *fa, *fb, *scrA, *scrB, *cntA, *cntB, *flbuf;
    cudaGetSymbolAddress((void**)&fa,   g_fa);
    cudaGetSymbolAddress((void**)&fb,   g_fb);
    cudaGetSymbolAddress((void**)&scrA, g_scrA);
    cudaGetSymbolAddress((void**)&scrB, g_scrB);
    cudaGetSymbolAddress((void**)&cntA, g_cntA);
    cudaGetSymbolAddress((void**)&cntB, g_cntB);
    cudaGetSymbolAddress((void**)&flbuf, g_fl);

    const int Cin[4]  = {3, 16, 32, 64};
    const int Cout[4] = {16, 32, 64, 128};
    const int Hin[4]  = {512, 256, 128, 64};

    size_t regOff[4];
    float* fl[4];
    {
        size_t a = 0, f = 0;
        for (int L = 0; L < 4; L++) {
            regOff[L] = a;
            int ho = Hin[L] / 2;
            a += (size_t)NB * Cout[L] * (ho + 2) * (ho + 2);
            fl[L] = flbuf + f;
            f += (size_t)NB * 2 * ho * ho;
        }
    }
    float* scrP[4] = {scrA, scrB, scrA, scrB};
    float* cntP[4] = {cntA, cntB, cntA, cntB};

    // ---- fork side stream ----
    cudaEventRecord(evFork, 0);
    cudaStreamWaitEvent(s2, evFork, 0);

    // ---- side stream: borders (merged), first flow halve, first memsets ----
    {
        BorderJobs J{};
        int nj = 0;
        int maxtot = 0;
        for (int L = 0; L < 4; L++) {
            int ho = Hin[L] / 2;
            J.sel[nj] = 0; J.off[nj] = (long long)regOff[L];
            J.NC[nj] = NB * Cout[L]; J.H[nj] = ho;
            int tot = J.NC[nj] * (2 * (ho + 2) + 2 * ho);
            if (tot > maxtot) maxtot = tot;
            nj++;
            if (L < 3) {
                J.sel[nj] = 1; J.off[nj] = (long long)regOff[L];
                J.NC[nj] = NB * Cout[L]; J.H[nj] = ho;
                nj++;
            }
        }
        J.njobs = nj;
        dim3 grd((maxtot + 255) / 256, nj);
        zero_borders_all<<<grd, 256, 0, s2>>>(fa, fb, J);
    }

    // flow halving chain + per-level memsets + evPre records on s2
    {
        int ho0 = Hin[0] / 2;
        halve_flow_kernel<<<(NB * 2 * ho0 * ho0 + 255) / 256, 256, 0, s2>>>(
            flow, fl[0], ho0, ho0);
        cudaMemsetAsync(scrP[0], 0, (size_t)NB * Cout[0] * ho0 * ho0 * sizeof(float), s2);
        cudaMemsetAsync(cntP[0], 0, (size_t)NB * ho0 * ho0 * sizeof(float), s2);
        cudaEventRecord(evPre[0], s2);

        for (int L = 1; L < 4; L++) {
            int ho = Hin[L] / 2;
            halve_flow_kernel<<<(NB * 2 * ho * ho + 255) / 256, 256, 0, s2>>>(
                fl[L - 1], fl[L], ho, ho);
        }
        int ho1 = Hin[1] / 2;
        cudaMemsetAsync(scrP[1], 0, (size_t)NB * Cout[1] * ho1 * ho1 * sizeof(float), s2);
        cudaMemsetAsync(cntP[1], 0, (size_t)NB * ho1 * ho1 * sizeof(float), s2);
        cudaEventRecord(evPre[1], s2);
    }

    // ---- main stream: conv chain; side stream: transpose + future memsets ----
    size_t off = 0;
    size_t outOff[4];
    for (int L = 0; L < 4; L++) { outOff[L] = off; off += (size_t)NB * Cout[L] * (Hin[L] / 2) * (Hin[L] / 2); }

    for (int L = 0; L < 4; L++) {
        const int ci = Cin[L], co = Cout[L], hi = Hin[L], ho = hi / 2;
        const float* wA = (const float*)d_in[2 + 6 * L + 0];
        const float* bA = (const float*)d_in[2 + 6 * L + 1];
        const float* aA = (const float*)d_in[2 + 6 * L + 2];
        const float* wB = (const float*)d_in[2 + 6 * L + 3];
        const float* bB = (const float*)d_in[2 + 6 * L + 4];
        const float* aB = (const float*)d_in[2 + 6 * L + 5];

        const int po = ho + 2;
        const size_t planeO = (size_t)po * po;
        float* faL = fa + regOff[L] + po + 1;
        float* fbL = fb + regOff[L] + po + 1;

        // --- conv_a: stride 2 (main stream) ---
        {
            dim3 blk(32, 8);
            dim3 grd(ho / 32, ho / 32, NB * (co / 4));
            size_t sm = 4 * ci * 9 * sizeof(float);
            if (L == 0) {
                conv3x3_prelu<2, 4, true, false, 3><<<grd, blk, sm>>>(
                    img, wA, bA, aA, faL, ci, co, hi, hi,
                    hi, (size_t)hi * hi, po, planeO, nullptr, nullptr, nullptr);
            } else {
                const int pi = hi + 2;
                const float* inL = fb + regOff[L - 1] + pi + 1;
                conv3x3_prelu<2, 4, false, false, 3><<<grd, blk, sm>>>(
                    inL, wA, bA, aA, faL, ci, co, hi, hi,
                    pi, (size_t)pi * pi, po, planeO, nullptr, nullptr, nullptr);
            }
        }

        // wait for flow + memsets for this level
        cudaStreamWaitEvent(0, evPre[L], 0);

        // --- conv_b with fused splat (main stream) ---
        {
            dim3 blk(32, 8);
            size_t sm = 4 * co * 9 * sizeof(float);
            if (ho >= 64) {
                dim3 grd(ho / 32, ho / 64, NB * (co / 4));
                conv3x3_prelu<1, 8, false, true, 4><<<grd, blk, sm>>>(
                    faL, wB, bB, aB, fbL, co, co, ho, ho,
                    po, planeO, po, planeO, fl[L], scrP[L], cntP[L]);
            } else {
                dim3 grd(ho / 32, ho / 32, NB * (co / 4));
                conv3x3_prelu<1, 4, false, true, 4><<<grd, blk, sm>>>(
                    faL, wB, bB, aB, fbL, co, co, ho, ho,
                    po, planeO, po, planeO, fl[L], scrP[L], cntP[L]);
            }
        }
        cudaEventRecord(evB[L], 0);

        // --- side stream: transpose this level; then memset for L+2 ---
        cudaStreamWaitEvent(s2, evB[L], 0);
        {
            int HW = ho * ho;
            dim3 blk(32, 8);
            dim3 grd(HW / 32, (co + 31) / 32, NB);
            norm_transpose<<<grd, blk, 0, s2>>>(scrP[L], cntP[L], out + outOff[L], co, HW);
        }
        if (L + 2 < 4) {
            int ho2 = Hin[L + 2] / 2;
            cudaMemsetAsync(scrP[L + 2], 0,
                            (size_t)NB * Cout[L + 2] * ho2 * ho2 * sizeof(float), s2);
            cudaMemsetAsync(cntP[L + 2], 0,
                            (size_t)NB * ho2 * ho2 * sizeof(float), s2);
            cudaEventRecord(evPre[L + 2], s2);
        }
    }

    // ---- join ----
    cudaEventRecord(evJoin, s2);
    cudaStreamWaitEvent(0, evJoin, 0);
}